// round 1
// baseline (speedup 1.0000x reference)
#include <cuda_runtime.h>
#include <cstdint>

#define N_NODES 50000
#define E_EDGES 800000
#define S_SAMP  4
#define D_OUT   128
#define MAIN_BLOCKS 6250   // N_NODES / 8

// ---------------- scratch (static device globals; no allocs) ----------------
__device__ unsigned int g_eps_pack[S_SAMP * N_NODES];      // [n][s] packed bits
__device__ int   g_deg[N_NODES];
__device__ int   g_off[N_NODES + 1];
__device__ int   g_cursor[N_NODES];
__device__ int   g_csr[E_EDGES];
__device__ float g_q[(size_t)N_NODES * 128];               // projected shared features
__device__ float g_part[(size_t)MAIN_BLOCKS * S_SAMP * 128];
__device__ float g_part2[64 * S_SAMP * 128];
__device__ float g_means[S_SAMP * 128];

// ---------------- f32x2 packed math helpers ----------------
__device__ __forceinline__ unsigned long long f2pack(float lo, float hi) {
    unsigned long long r;
    asm("mov.b64 %0, {%1, %2};" : "=l"(r) : "f"(lo), "f"(hi));
    return r;
}
__device__ __forceinline__ void f2fma(unsigned long long& d, unsigned long long a, unsigned long long b) {
    asm("fma.rn.f32x2 %0, %1, %2, %0;" : "+l"(d) : "l"(a), "l"(b));
}
__device__ __forceinline__ void f2unpack(float& lo, float& hi, unsigned long long v) {
    asm("mov.b64 {%0, %1}, %2;" : "=f"(lo), "=f"(hi) : "l"(v));
}

// ---------------- tiny setup kernels ----------------
__global__ void zero_deg_kernel() {
    int i = blockIdx.x * blockDim.x + threadIdx.x;
    if (i < N_NODES) g_deg[i] = 0;
}

// one warp per (s,n): pack 32 Bernoulli floats into a bitmask
__global__ void pack_kernel(const float* __restrict__ eps) {
    int g = blockIdx.x * 8 + (threadIdx.x >> 5);
    int lane = threadIdx.x & 31;
    if (g >= S_SAMP * N_NODES) return;
    int s = g / N_NODES;
    int n = g - s * N_NODES;
    float v = eps[(size_t)g * 32 + lane];
    unsigned m = __ballot_sync(0xffffffffu, v > 0.5f);
    if (lane == 0) g_eps_pack[n * 4 + s] = m;
}

__global__ void degree_kernel(const int* __restrict__ dst) {
    int e = blockIdx.x * blockDim.x + threadIdx.x;
    if (e < E_EDGES) atomicAdd(&g_deg[dst[e]], 1);
}

// single-block scan of degrees -> offsets
__global__ void scan_kernel() {
    __shared__ int warp_sums[32];
    __shared__ int s_carry;
    int tid = threadIdx.x, lane = tid & 31, wid = tid >> 5;
    if (tid == 0) { s_carry = 0; g_off[0] = 0; }
    __syncthreads();
    for (int base = 0; base < N_NODES; base += 1024) {
        int i = base + tid;
        int v = (i < N_NODES) ? g_deg[i] : 0;
        int x = v;
        #pragma unroll
        for (int d = 1; d < 32; d <<= 1) {
            int t = __shfl_up_sync(0xffffffffu, x, d);
            if (lane >= d) x += t;
        }
        if (lane == 31) warp_sums[wid] = x;
        __syncthreads();
        if (wid == 0) {
            int w = warp_sums[lane];
            #pragma unroll
            for (int d = 1; d < 32; d <<= 1) {
                int t = __shfl_up_sync(0xffffffffu, w, d);
                if (lane >= d) w += t;
            }
            warp_sums[lane] = w;
        }
        __syncthreads();
        int off = s_carry + ((wid > 0) ? warp_sums[wid - 1] : 0) + x;
        if (i < N_NODES) g_off[i + 1] = off;
        __syncthreads();
        if (tid == 1023) s_carry += warp_sums[31];
        __syncthreads();
    }
}

__global__ void cursor_init_kernel() {
    int i = blockIdx.x * blockDim.x + threadIdx.x;
    if (i < N_NODES) g_cursor[i] = g_off[i];
}

__global__ void fill_kernel(const int* __restrict__ src, const int* __restrict__ dst) {
    int e = blockIdx.x * blockDim.x + threadIdx.x;
    if (e < E_EDGES) {
        int d = dst[e];
        int pos = atomicAdd(&g_cursor[d], 1);
        g_csr[pos] = src[e];
    }
}

// ---------------- q = [X,h] @ W_shared  (N x 128) ----------------
// block: 256 threads = (32 lanes x 8), 32 nodes per block
__global__ void __launch_bounds__(256) q_kernel(const float* __restrict__ X,
                                                const float* __restrict__ H,
                                                const float* __restrict__ W) {
    __shared__ float  xs[32][128];     // 16 KB: node-local shared features
    __shared__ float4 Ws[32][32];      // 16 KB: one 32-row chunk of W (128 cols)
    int tid = threadIdx.x, lane = tid & 31, wy = tid >> 5;
    int node0 = blockIdx.x * 32;

    for (int idx = tid; idx < 32 * 128; idx += 256) {
        int nn = idx >> 7, k = idx & 127;
        int n = node0 + nn;
        float v = 0.f;
        if (n < N_NODES) v = (k < 96) ? X[(size_t)n * 96 + k] : H[(size_t)n * 32 + (k - 96)];
        xs[nn][k] = v;
    }

    unsigned long long accA[4], accB[4];
    #pragma unroll
    for (int j = 0; j < 4; j++) { accA[j] = f2pack(0.f, 0.f); accB[j] = f2pack(0.f, 0.f); }

    for (int kc = 0; kc < 4; kc++) {
        __syncthreads();
        for (int idx = tid; idx < 32 * 128; idx += 256) {
            int kk = idx >> 7, c = idx & 127;
            int k = kc * 32 + kk;
            int wrow = (k < 96) ? k : (k + 32);   // skip epsilon rows 96..127 of W
            ((float*)Ws)[idx] = W[wrow * 128 + c];
        }
        __syncthreads();
        #pragma unroll
        for (int kk = 0; kk < 32; kk++) {
            float4 w4 = Ws[kk][lane];
            unsigned long long wA = f2pack(w4.x, w4.y), wB = f2pack(w4.z, w4.w);
            #pragma unroll
            for (int j = 0; j < 4; j++) {
                float xv = xs[wy + j * 8][kc * 32 + kk];
                unsigned long long xp = f2pack(xv, xv);
                f2fma(accA[j], xp, wA);
                f2fma(accB[j], xp, wB);
            }
        }
    }
    #pragma unroll
    for (int j = 0; j < 4; j++) {
        int n = node0 + wy + j * 8;
        if (n < N_NODES) {
            float4 r;
            f2unpack(r.x, r.y, accA[j]);
            f2unpack(r.z, r.w, accB[j]);
            *(float4*)&g_q[(size_t)n * 128 + 4 * lane] = r;
        }
    }
}

// ---------------- main: CSR neighbor-sum + eps-GEMV + relu + block mean ----------------
// block: 256 threads = 8 warps = 8 nodes
__global__ void __launch_bounds__(256) main_kernel(const float* __restrict__ bias,
                                                   const float* __restrict__ W,
                                                   const float* __restrict__ gin_eps) {
    __shared__ float4 Weps[32][32];    // 16 KB: W rows 96..127 (epsilon block)
    __shared__ float  bsm[128];
    __shared__ float  zs[8 * 4 * 128]; // 16 KB: per-warp per-sample relu(z)
    int tid = threadIdx.x, lane = tid & 31, wid = tid >> 5;

    for (int idx = tid; idx < 32 * 128; idx += 256) {
        int f = idx >> 7, c = idx & 127;
        ((float*)Weps)[idx] = W[(96 + f) * 128 + c];
    }
    if (tid < 128) bsm[tid] = bias[tid];
    __syncthreads();

    int n = blockIdx.x * 8 + wid;       // exact: 6250*8 == N_NODES
    float c0 = 1.f + *gin_eps;

    float4 acc = *(const float4*)&g_q[(size_t)n * 128 + 4 * lane];
    acc.x *= c0; acc.y *= c0; acc.z *= c0; acc.w *= c0;

    uint4 selfp = *(const uint4*)&g_eps_pack[n * 4];
    int cnt0 = 0, cnt1 = 0, cnt2 = 0, cnt3 = 0;

    int e0 = g_off[n], e1 = g_off[n + 1];
    for (int e = e0; e < e1; e++) {
        int j = g_csr[e];
        float4 qv = *(const float4*)&g_q[(size_t)j * 128 + 4 * lane];
        acc.x += qv.x; acc.y += qv.y; acc.z += qv.z; acc.w += qv.w;
        uint4 p = *(const uint4*)&g_eps_pack[j * 4];
        cnt0 += (p.x >> lane) & 1;
        cnt1 += (p.y >> lane) & 1;
        cnt2 += (p.z >> lane) & 1;
        cnt3 += (p.w >> lane) & 1;
    }

    float coeff[4];
    coeff[0] = (float)cnt0 + c0 * (float)((selfp.x >> lane) & 1);
    coeff[1] = (float)cnt1 + c0 * (float)((selfp.y >> lane) & 1);
    coeff[2] = (float)cnt2 + c0 * (float)((selfp.z >> lane) & 1);
    coeff[3] = (float)cnt3 + c0 * (float)((selfp.w >> lane) & 1);

    float4 b4 = ((const float4*)bsm)[lane];
    unsigned long long zA[4], zB[4];
    #pragma unroll
    for (int s = 0; s < 4; s++) {
        zA[s] = f2pack(acc.x + b4.x, acc.y + b4.y);
        zB[s] = f2pack(acc.z + b4.z, acc.w + b4.w);
    }
    #pragma unroll
    for (int f = 0; f < 32; f++) {
        float4 w4 = Weps[f][lane];
        unsigned long long wA = f2pack(w4.x, w4.y), wB = f2pack(w4.z, w4.w);
        #pragma unroll
        for (int s = 0; s < 4; s++) {
            float cf = __shfl_sync(0xffffffffu, coeff[s], f);
            unsigned long long cf2 = f2pack(cf, cf);
            f2fma(zA[s], cf2, wA);
            f2fma(zB[s], cf2, wB);
        }
    }
    #pragma unroll
    for (int s = 0; s < 4; s++) {
        float4 r;
        f2unpack(r.x, r.y, zA[s]);
        f2unpack(r.z, r.w, zB[s]);
        r.x = fmaxf(r.x, 0.f); r.y = fmaxf(r.y, 0.f);
        r.z = fmaxf(r.z, 0.f); r.w = fmaxf(r.w, 0.f);
        ((float4*)zs)[(wid * 4 + s) * 32 + lane] = r;
    }
    __syncthreads();

    // reduce the 8 nodes of this block -> per-block partial sums [4][128]
    for (int p = tid; p < 512; p += 256) {
        float v = 0.f;
        #pragma unroll
        for (int w = 0; w < 8; w++) v += zs[w * 512 + p];
        g_part[(size_t)blockIdx.x * 512 + p] = v;
    }
}

// ---------------- two-stage deterministic mean reduction ----------------
__global__ void reduce1_kernel() {
    int tid = threadIdx.x;            // 512
    int b = blockIdx.x;               // 64
    float v = 0.f;
    for (int i = b; i < MAIN_BLOCKS; i += 64) v += g_part[(size_t)i * 512 + tid];
    g_part2[b * 512 + tid] = v;
}
__global__ void reduce2_kernel() {
    int tid = threadIdx.x;            // 512
    float v = 0.f;
    #pragma unroll
    for (int i = 0; i < 64; i++) v += g_part2[i * 512 + tid];
    g_means[tid] = fmaxf(v * (1.f / (float)N_NODES), 0.f);  // mean + outer relu
}

// ---------------- broadcast means -> output [S,N,128] ----------------
__global__ void bcast_kernel(float4* __restrict__ out) {
    int idx = blockIdx.x * blockDim.x + threadIdx.x;       // S*N*32 float4s
    if (idx < S_SAMP * N_NODES * 32) {
        int s = idx / (N_NODES * 32);
        int c4 = idx & 31;
        out[idx] = ((const float4*)g_means)[s * 32 + c4];
    }
}

// ---------------- launch ----------------
extern "C" void kernel_launch(void* const* d_in, const int* in_sizes, int n_in,
                              void* d_out, int out_size) {
    const float* X    = (const float*)d_in[0];
    const float* H    = (const float*)d_in[1];
    const float* eps  = (const float*)d_in[2];
    const float* W    = (const float*)d_in[3];
    const float* bias = (const float*)d_in[4];
    const float* geps = (const float*)d_in[5];
    const int*   src  = (const int*)d_in[6];
    const int*   dst  = (const int*)d_in[7];

    zero_deg_kernel<<<(N_NODES + 255) / 256, 256>>>();
    pack_kernel<<<(S_SAMP * N_NODES + 7) / 8, 256>>>(eps);
    degree_kernel<<<(E_EDGES + 255) / 256, 256>>>(dst);
    scan_kernel<<<1, 1024>>>();
    cursor_init_kernel<<<(N_NODES + 255) / 256, 256>>>();
    fill_kernel<<<(E_EDGES + 255) / 256, 256>>>(src, dst);
    q_kernel<<<(N_NODES + 31) / 32, 256>>>(X, H, W);
    main_kernel<<<MAIN_BLOCKS, 256>>>(bias, W, geps);
    reduce1_kernel<<<64, 512>>>();
    reduce2_kernel<<<1, 512>>>();
    bcast_kernel<<<(S_SAMP * N_NODES * 32 + 255) / 256, 256>>>((float4*)d_out);

    long long main_elems = (long long)S_SAMP * N_NODES * 128;
    if ((long long)out_size > main_elems) {
        long long eps_elems = (long long)S_SAMP * N_NODES * 32;
        long long avail = (long long)out_size - main_elems;
        if (avail > eps_elems) avail = eps_elems;
        cudaMemcpyAsync((float*)d_out + main_elems, eps,
                        (size_t)avail * sizeof(float), cudaMemcpyDeviceToDevice);
    }
}